// round 2
// baseline (speedup 1.0000x reference)
#include <cuda_runtime.h>
#include <math.h>
#include <stdint.h>

#define NF 3000
#define NB 1500
#define KNB 64

// -------------------- global scratch (no runtime allocation allowed) ----------
__device__ float g_p1[NF * 3];
__device__ float g_ff[NF * 9];

__device__ int   g_idxF[NF * KNB];
__device__ int   g_cbF [NF * KNB];
__device__ float g_w8F [NF * KNB * 8];
__device__ int   g_cntF[NF];

__device__ int   g_idxB[NF * KNB];
__device__ int   g_cbB [NF * KNB];
__device__ float g_w8B [NF * KNB * 8];
__device__ int   g_cntB[NF];

__device__ float g_out0[NF * 3 * 96];
__device__ float g_out1[NF * 3 * 64];
__device__ float g_out2[NF * 3 * 64];
__device__ float g_out3[NF * 3 * 64];
__device__ float g_out4[NF * 3 * 3];

__device__ float g_A[(size_t)NF * 3 * 64 * 96];   // GEMM input scratch (max layer1)

// -------------------- helpers -------------------------------------------------
__device__ __forceinline__ float sgnf(float v) {
    return (v > 0.f) ? 1.f : ((v < 0.f) ? -1.f : 0.f);
}

// Per-edge weight computation: offset (dx,dy,dz) = p_in[j] - p_out[n]
__device__ void edge_weights(float dx, float dy, float dz, float* w8, int* cbase)
{
    const float inv_r = 1.f / 3.f;     // radius = EXTENT*0.5 = 3.0
    float x = dx * inv_r, y = dy * inv_r, z = dz * inv_r;
    float sq = (x * x + y * y) + z * z;

    float win = 1.f - sq;
    win = win * win * win;
    win = fminf(fmaxf(win, 0.f), 1.f);

    // _ball_to_cube
    float norm  = sqrtf(fmaxf(sq, 1e-8f));
    float xy_sq = x * x + y * y;
    bool  polar = (1.25f * z * z > xy_sq);
    float s_p = sqrtf(3.f * norm / (norm + fabsf(z) + 1e-8f));
    float s_e = norm / sqrtf(fmaxf(xy_sq, 1e-8f));
    float cx = polar ? x * s_p : x * s_e;
    float cy = polar ? y * s_p : y * s_e;
    float cz = polar ? sgnf(z) * norm : 1.5f * z;

    float nxy = sqrtf(fmaxf(cx * cx + cy * cy, 1e-8f));
    bool  xdom = (fabsf(cy) <= fabsf(cx));
    float sx = (fabsf(cx) > 1e-8f) ? cx : 1.f;
    float sy = (fabsf(cy) > 1e-8f) ? cy : 1.f;
    const float FOPI = 1.27323954473516268615f;  // 4/pi
    float bx1 = sgnf(cx) * nxy;
    float by1 = bx1 * FOPI * atanf(cy / sx);
    float by2 = sgnf(cy) * nxy;
    float bx2 = by2 * FOPI * atanf(cx / sy);
    float bx = xdom ? bx1 : bx2;
    float by = xdom ? by1 : by2;
    if (cx * cx + cy * cy < 1e-8f) { bx = 0.f; by = 0.f; }
    float bz = cz;
    if (sq < 1e-8f) { bx = 0.f; by = 0.f; bz = 0.f; }

    float bb[3] = {bx, by, bz};
    float f[3];
    int   c0[3];
#pragma unroll
    for (int ax = 0; ax < 3; ax++) {
        float co = (bb[ax] * 0.5f + 0.5f) * 3.f;       // (KS-1)=3
        co = fminf(fmaxf(co, 0.f), 3.f);
        int ci = (int)floorf(co);
        ci = min(max(ci, 0), 2);
        c0[ax] = ci;
        f[ax] = co - (float)ci;
    }
    *cbase = (c0[0] * 4 + c0[1]) * 4 + c0[2];
#pragma unroll
    for (int r = 0; r < 8; r++) {
        int i = (r >> 2) & 1, j = (r >> 1) & 1, l = r & 1;
        float w = (i ? f[0] : 1.f - f[0]) * (j ? f[1] : 1.f - f[1]) * (l ? f[2] : 1.f - f[2]);
        w8[r] = w * win;
    }
}

// -------------------- kernel 1: prep -----------------------------------------
__global__ void prep_kernel(const float* __restrict__ p0, const float* __restrict__ v0,
                            const float* __restrict__ a, const float* __restrict__ other,
                            const float* __restrict__ v0e)
{
    int n = blockIdx.x * blockDim.x + threadIdx.x;
    if (n >= NF) return;
#pragma unroll
    for (int j = 0; j < 3; j++) {
        float v0v = v0[n * 3 + j], av = a[n * 3 + j];
        float v1 = v0v + 0.1f * av;
        float p1 = p0[n * 3 + j] + 0.1f * (v0v + v1) * 0.5f;
        g_p1[n * 3 + j] = p1;
        g_ff[n * 9 + 0 + j] = v1;                // s=0 : v1
        g_ff[n * 9 + 3 + j] = other[n * 3 + j];  // s=1 : other_feats
        g_ff[n * 9 + 6 + j] = v0e[n * 3 + j];    // s=2 : v0_enc
    }
}

// -------------------- kernel 2: neighbor build (fluid or box) -----------------
__global__ void nbr_kernel(const float* __restrict__ pts, int npts,
                           const float* __restrict__ mask, int self_exclude,
                           int* __restrict__ idx_out, int* __restrict__ cb_out,
                           float* __restrict__ w8_out, int* __restrict__ cnt_out)
{
    int n = blockIdx.x;
    __shared__ float sd2[512];
    __shared__ int   sidx[512];
    __shared__ int   scnt;
    float qx = g_p1[n * 3], qy = g_p1[n * 3 + 1], qz = g_p1[n * 3 + 2];
    if (threadIdx.x == 0) scnt = 0;
    __syncthreads();

    for (int j = threadIdx.x; j < npts; j += blockDim.x) {
        if (self_exclude && j == n) continue;
        if (mask && mask[j] <= 0.f) continue;
        float dx = pts[j * 3] - qx, dy = pts[j * 3 + 1] - qy, dz = pts[j * 3 + 2] - qz;
        float d2 = (dx * dx + dy * dy) + dz * dz;
        if (d2 < 9.0f) {
            int p = atomicAdd(&scnt, 1);
            if (p < 512) { sd2[p] = d2; sidx[p] = j; }
        }
    }
    __syncthreads();
    int cnt = min(scnt, 512);

    if (cnt > 1) {
        int P = 1;
        while (P < cnt) P <<= 1;
        for (int i = cnt + threadIdx.x; i < P; i += blockDim.x) { sd2[i] = 3.0e38f; sidx[i] = 0x7fffffff; }
        __syncthreads();
        for (int k = 2; k <= P; k <<= 1) {
            for (int j2 = k >> 1; j2 > 0; j2 >>= 1) {
                for (int i = threadIdx.x; i < P; i += blockDim.x) {
                    int ixj = i ^ j2;
                    if (ixj > i) {
                        float a = sd2[i], b = sd2[ixj];
                        int ia = sidx[i], ib = sidx[ixj];
                        bool agtb = (a > b) || ((a == b) && (ia > ib));
                        bool up = ((i & k) == 0);
                        if (agtb == up) { sd2[i] = b; sd2[ixj] = a; sidx[i] = ib; sidx[ixj] = ia; }
                    }
                }
                __syncthreads();
            }
        }
    }

    if (cnt > KNB) cnt = KNB;
    if (threadIdx.x == 0) cnt_out[n] = cnt;
    if ((int)threadIdx.x < cnt) {
        int j = sidx[threadIdx.x];
        float dx = pts[j * 3] - qx, dy = pts[j * 3 + 1] - qy, dz = pts[j * 3 + 2] - qz;
        float w8[8];
        int cb;
        edge_weights(dx, dy, dz, w8, &cb);
        int e = n * KNB + threadIdx.x;
        idx_out[e] = j;
        cb_out[e] = cb;
#pragma unroll
        for (int r = 0; r < 8; r++) w8_out[e * 8 + r] = w8[r];
    }
}

// -------------------- kernel 3: phase-2 (cf + co + df -> out0) ----------------
__global__ void phase2_kernel(const float* __restrict__ box_feats,
                              const float* __restrict__ k0f, const float* __restrict__ b0f,
                              const float* __restrict__ k0o, const float* __restrict__ b0o,
                              const float* __restrict__ wdf, const float* __restrict__ bdf)
{
    int n = blockIdx.x, tid = threadIdx.x;
    __shared__ float cF[576];   // 64 cells x 9 (s*3+c)
    __shared__ float cB[64];
    for (int i = tid; i < 576; i += blockDim.x) cF[i] = 0.f;
    if (tid < 64) cB[tid] = 0.f;
    __syncthreads();

    int cntF = g_cntF[n];
    for (int e = tid; e < cntF; e += blockDim.x) {
        int j = g_idxF[n * KNB + e];
        int cb = g_cbF[n * KNB + e];
        const float* w = &g_w8F[(n * KNB + e) * 8];
        float fj[9];
#pragma unroll
        for (int c = 0; c < 9; c++) fj[c] = g_ff[j * 9 + c];
#pragma unroll
        for (int r = 0; r < 8; r++) {
            int l = cb + ((r >> 2) & 1) * 16 + ((r >> 1) & 1) * 4 + (r & 1);
            float wr = w[r];
#pragma unroll
            for (int c = 0; c < 9; c++) atomicAdd(&cF[l * 9 + c], wr * fj[c]);
        }
    }
    int cntB = g_cntB[n];
    for (int e = tid; e < cntB; e += blockDim.x) {
        int j = g_idxB[n * KNB + e];
        int cb = g_cbB[n * KNB + e];
        const float* w = &g_w8B[(n * KNB + e) * 8];
        float bf = box_feats[j];
#pragma unroll
        for (int r = 0; r < 8; r++) {
            int l = cb + ((r >> 2) & 1) * 16 + ((r >> 1) & 1) * 4 + (r & 1);
            atomicAdd(&cB[l], w[r] * bf);
        }
    }
    __syncthreads();

    if (tid < 96) {
        int s = tid / 32, o = tid % 32;
        float co = b0o[o];
        for (int l = 0; l < 64; l++) co += cB[l] * k0o[l * 32 + o];
        float cf = b0f[o];
        for (int l = 0; l < 64; l++) {
#pragma unroll
            for (int c = 0; c < 3; c++) cf += cF[l * 9 + s * 3 + c] * k0f[(l * 3 + c) * 32 + o];
        }
        float df = bdf[o];
#pragma unroll
        for (int c = 0; c < 3; c++) df += g_ff[n * 9 + s * 3 + c] * wdf[c * 32 + o];
        int base = n * 288 + s * 96;
        g_out0[base + o]      = co;   // concat order: [co, cf, df]
        g_out0[base + 32 + o] = cf;
        g_out0[base + 64 + o] = df;
    }
}

// -------------------- kernel 4: per-point cell scatter (fluid edges) ----------
// prev: 3000 rows of (3*C) pre-relu features. Writes A (9000 x 64C), row = n*3+s.
__global__ void scatter_kernel(const float* __restrict__ prev, float* __restrict__ Aout, int C)
{
    int n = blockIdx.x;
    int SC = 3 * C;
    int tid = threadIdx.x;         // one channel (s*C+c) per thread, blockDim = SC
    extern __shared__ float cell[];   // [64][SC]
    __shared__ float ew[KNB * 8];
    __shared__ int   ej[KNB];
    __shared__ int   ecb[KNB];

    for (int l = 0; l < 64; l++) cell[l * SC + tid] = 0.f;
    int cnt = g_cntF[n];
    if (tid < cnt) { ej[tid] = g_idxF[n * KNB + tid]; ecb[tid] = g_cbF[n * KNB + tid]; }
    for (int i = tid; i < cnt * 8; i += blockDim.x) ew[i] = g_w8F[n * KNB * 8 + i];
    __syncthreads();

    for (int e = 0; e < cnt; e++) {
        float h = fmaxf(prev[(size_t)ej[e] * SC + tid], 0.f);
        int cb = ecb[e];
        const float* w = &ew[e * 8];
        cell[(cb + 0)  * SC + tid] += w[0] * h;
        cell[(cb + 1)  * SC + tid] += w[1] * h;
        cell[(cb + 4)  * SC + tid] += w[2] * h;
        cell[(cb + 5)  * SC + tid] += w[3] * h;
        cell[(cb + 16) * SC + tid] += w[4] * h;
        cell[(cb + 17) * SC + tid] += w[5] * h;
        cell[(cb + 20) * SC + tid] += w[6] * h;
        cell[(cb + 21) * SC + tid] += w[7] * h;
    }
    __syncthreads();

    int s = tid / C, c = tid % C;
    int Kdim = 64 * C;
    float* dst = Aout + (size_t)(n * 3 + s) * Kdim + c;
    for (int l = 0; l < 64; l++) dst[l * C] = cell[l * SC + tid];
}

// -------------------- kernel 5: GEMM + dense + bias + residual ----------------
// Out[row,o] = sum_k A[row,k]*Bk[k,o] + sum_c relu(prev[row,c])*wd[c,o] + bc[o]+bd[o]
//              + (res ? prev[row,o] : 0).  N = 64 cols fixed.
__global__ void __launch_bounds__(256) gemm_kernel(
    const float* __restrict__ A, const float* __restrict__ Bk,
    const float* __restrict__ prev, const float* __restrict__ wd,
    const float* __restrict__ bc, const float* __restrict__ bd,
    float* __restrict__ Out, int M, int K, int C, int res)
{
    __shared__ float As[16][64];
    __shared__ float Bs[16][64];
    int tid = threadIdx.x;
    int tx = tid & 15, ty = tid >> 4;
    int rowBase = blockIdx.x * 64;
    float acc[4][4];
#pragma unroll
    for (int i = 0; i < 4; i++)
#pragma unroll
        for (int j = 0; j < 4; j++) acc[i][j] = 0.f;

    for (int seg = 0; seg < 2; seg++) {
        const float* Ag = seg ? prev : A;
        const float* Bg = seg ? wd : Bk;
        int Ks = seg ? C : K;
        for (int k0 = 0; k0 < Ks; k0 += 16) {
            int r = tid >> 2;
            int kq = (tid & 3) * 4;
            int grow = rowBase + r;
            if (grow >= M) grow = M - 1;
            float4 av = *(const float4*)(Ag + (size_t)grow * Ks + (k0 + kq));
            if (seg) {
                av.x = fmaxf(av.x, 0.f); av.y = fmaxf(av.y, 0.f);
                av.z = fmaxf(av.z, 0.f); av.w = fmaxf(av.w, 0.f);
            }
            As[kq + 0][r] = av.x; As[kq + 1][r] = av.y;
            As[kq + 2][r] = av.z; As[kq + 3][r] = av.w;

            int kb = tid >> 4;
            int cq = (tid & 15) * 4;
            float4 bv = *(const float4*)(Bg + (size_t)(k0 + kb) * 64 + cq);
            *(float4*)&Bs[kb][cq] = bv;
            __syncthreads();

#pragma unroll
            for (int kk = 0; kk < 16; kk++) {
                float4 a4 = *(float4*)&As[kk][ty * 4];
                float4 b4 = *(float4*)&Bs[kk][tx * 4];
                float ar[4] = {a4.x, a4.y, a4.z, a4.w};
                float br[4] = {b4.x, b4.y, b4.z, b4.w};
#pragma unroll
                for (int i = 0; i < 4; i++)
#pragma unroll
                    for (int j = 0; j < 4; j++) acc[i][j] += ar[i] * br[j];
            }
            __syncthreads();
        }
    }

#pragma unroll
    for (int i = 0; i < 4; i++) {
        int row = rowBase + ty * 4 + i;
        if (row >= M) continue;
#pragma unroll
        for (int j = 0; j < 4; j++) {
            int col = tx * 4 + j;
            float v = acc[i][j] + bc[col] + bd[col];
            if (res) v += prev[(size_t)row * C + col];
            Out[(size_t)row * 64 + col] = v;
        }
    }
}

// -------------------- kernel 6: last layer (64C -> 3) -------------------------
__global__ void out4_kernel(const float* __restrict__ A, const float* __restrict__ kern,
                            const float* __restrict__ prev, const float* __restrict__ wd,
                            const float* __restrict__ bc, const float* __restrict__ bd,
                            float* __restrict__ out4, int M, int K)
{
    int warp = (blockIdx.x * blockDim.x + threadIdx.x) >> 5;
    int lane = threadIdx.x & 31;
    if (warp >= M) return;
    float a0 = 0.f, a1 = 0.f, a2 = 0.f;
    const float* Ar = A + (size_t)warp * K;
    for (int k = lane; k < K; k += 32) {
        float av = Ar[k];
        a0 += av * kern[k * 3 + 0];
        a1 += av * kern[k * 3 + 1];
        a2 += av * kern[k * 3 + 2];
    }
    const float* pr = prev + (size_t)warp * 64;
    for (int c = lane; c < 64; c += 32) {
        float h = fmaxf(pr[c], 0.f);
        a0 += h * wd[c * 3 + 0];
        a1 += h * wd[c * 3 + 1];
        a2 += h * wd[c * 3 + 2];
    }
#pragma unroll
    for (int off = 16; off > 0; off >>= 1) {
        a0 += __shfl_down_sync(0xffffffffu, a0, off);
        a1 += __shfl_down_sync(0xffffffffu, a1, off);
        a2 += __shfl_down_sync(0xffffffffu, a2, off);
    }
    if (lane == 0) {
        out4[warp * 3 + 0] = a0 + bc[0] + bd[0];
        out4[warp * 3 + 1] = a1 + bc[1] + bd[1];
        out4[warp * 3 + 2] = a2 + bc[2] + bd[2];
    }
}

// -------------------- kernel 7: final outputs ---------------------------------
__global__ void final_kernel(const float* __restrict__ p0, const float* __restrict__ v0e,
                             float* __restrict__ outp)
{
    int n = blockIdx.x * blockDim.x + threadIdx.x;
    if (n >= NF) return;
#pragma unroll
    for (int j = 0; j < 3; j++) {
        float o0 = g_out4[n * 9 + j];                 // s=0 row
        float corr = o0 * 0.25f * (1.f / 16.f);
        float pc = g_p1[n * 3 + j] + corr;
        outp[n * 3 + j] = pc;                          // p_c
        outp[9000 + n * 3 + j] = (pc - p0[n * 3 + j]) / 0.1f;  // v_c
        outp[18000 + n * 6 + 0 + j] = g_out4[n * 9 + 3 + j] * 0.25f;  // m_matrix s=1
        outp[18000 + n * 6 + 3 + j] = g_out4[n * 9 + 6 + j] * 0.25f;  // m_matrix s=2
        outp[36000 + n * 3 + j] = v0e[n * 3 + j];      // state_feats
    }
}

// -------------------- launch --------------------------------------------------
template <typename T>
static T* sym_addr(const void* sym)
{
    void* p = nullptr;
    cudaGetSymbolAddress(&p, sym);
    return (T*)p;
}

extern "C" void kernel_launch(void* const* d_in, const int* in_sizes, int n_in,
                              void* d_out, int out_size)
{
    (void)n_in; (void)out_size;
    // Indices 0..15 are identical under both dict order and signature order.
    const float* v0e       = (const float*)d_in[1];
    const float* p0        = (const float*)d_in[2];
    const float* v0        = (const float*)d_in[3];
    const float* a         = (const float*)d_in[4];
    const float* other     = (const float*)d_in[5];
    const float* box       = (const float*)d_in[6];
    const float* box_feats = (const float*)d_in[7];
    const float* box_mask  = (const float*)d_in[9];
    const float* k0f = (const float*)d_in[10];
    const float* b0f = (const float*)d_in[11];
    const float* k0o = (const float*)d_in[12];
    const float* b0o = (const float*)d_in[13];
    const float* wdf = (const float*)d_in[14];
    const float* bdf = (const float*)d_in[15];

    // Resolve deep-layer weights 16..31 BY SIZE (robust to dict-order vs
    // signature-order metadata): kc1=64*96*64, kc2/kc3=64*64*64, kc4=64*64*3,
    // wd1=96*64, wd2/wd3=64*64, wd4=64*3, biases are 64 or 3 elems (all zero,
    // only consumed as bc+bd sums, so their pairing is irrelevant).
    const float* kcA[5] = {0, 0, 0, 0, 0};
    const float* wdA[5] = {0, 0, 0, 0, 0};
    const float* b64[6] = {0, 0, 0, 0, 0, 0};
    const float* b3[2]  = {0, 0};
    int n262 = 0, n4096 = 0, nb64 = 0, nb3 = 0;
    for (int i = 16; i < 32; i++) {
        const float* p = (const float*)d_in[i];
        switch (in_sizes[i]) {
            case 393216: kcA[1] = p; break;
            case 262144: if (n262++ == 0) kcA[2] = p; else kcA[3] = p; break;
            case 12288:  kcA[4] = p; break;
            case 6144:   wdA[1] = p; break;
            case 4096:   if (n4096++ == 0) wdA[2] = p; else wdA[3] = p; break;
            case 192:    wdA[4] = p; break;
            case 64:     if (nb64 < 6) b64[nb64++] = p; break;
            case 3:      if (nb3 < 2) b3[nb3++] = p; break;
            default: break;
        }
    }
    const float* bc1 = b64[0]; const float* bd1 = b64[1];
    const float* bc2 = b64[2]; const float* bd2 = b64[3];
    const float* bc3 = b64[4]; const float* bd3 = b64[5];
    const float* bc4 = b3[0];  const float* bd4 = b3[1];

    float* outp = (float*)d_out;

    float* pp1   = sym_addr<float>(g_p1);
    int*   pidxF = sym_addr<int>(g_idxF);
    int*   pcbF  = sym_addr<int>(g_cbF);
    float* pw8F  = sym_addr<float>(g_w8F);
    int*   pcntF = sym_addr<int>(g_cntF);
    int*   pidxB = sym_addr<int>(g_idxB);
    int*   pcbB  = sym_addr<int>(g_cbB);
    float* pw8B  = sym_addr<float>(g_w8B);
    int*   pcntB = sym_addr<int>(g_cntB);
    float* pout0 = sym_addr<float>(g_out0);
    float* pout1 = sym_addr<float>(g_out1);
    float* pout2 = sym_addr<float>(g_out2);
    float* pout3 = sym_addr<float>(g_out3);
    float* pout4 = sym_addr<float>(g_out4);
    float* pA    = sym_addr<float>(g_A);

    cudaFuncSetAttribute(scatter_kernel, cudaFuncAttributeMaxDynamicSharedMemorySize,
                         64 * 288 * (int)sizeof(float));

    prep_kernel<<<(NF + 127) / 128, 128>>>(p0, v0, a, other, v0e);
    nbr_kernel<<<NF, 128>>>(pp1, NF, nullptr, 1, pidxF, pcbF, pw8F, pcntF);
    nbr_kernel<<<NF, 128>>>(box, NB, box_mask, 0, pidxB, pcbB, pw8B, pcntB);
    phase2_kernel<<<NF, 128>>>(box_feats, k0f, b0f, k0o, b0o, wdf, bdf);

    const int Mrows = NF * 3;  // 9000
    const int gemmGrid = (Mrows + 63) / 64;

    // layer 1: C=96, K=6144, no residual
    scatter_kernel<<<NF, 288, 64 * 288 * sizeof(float)>>>(pout0, pA, 96);
    gemm_kernel<<<gemmGrid, 256>>>(pA, kcA[1], pout0, wdA[1], bc1, bd1, pout1, Mrows, 6144, 96, 0);

    // layer 2: C=64, K=4096, residual
    scatter_kernel<<<NF, 192, 64 * 192 * sizeof(float)>>>(pout1, pA, 64);
    gemm_kernel<<<gemmGrid, 256>>>(pA, kcA[2], pout1, wdA[2], bc2, bd2, pout2, Mrows, 4096, 64, 1);

    // layer 3: C=64, K=4096, residual
    scatter_kernel<<<NF, 192, 64 * 192 * sizeof(float)>>>(pout2, pA, 64);
    gemm_kernel<<<gemmGrid, 256>>>(pA, kcA[3], pout2, wdA[3], bc3, bd3, pout3, Mrows, 4096, 64, 1);

    // layer 4: C=64 -> 3 outputs
    scatter_kernel<<<NF, 192, 64 * 192 * sizeof(float)>>>(pout3, pA, 64);
    out4_kernel<<<(Mrows * 32 + 255) / 256, 256>>>(pA, kcA[4], pout3, wdA[4], bc4, bd4, pout4, Mrows, 4096);

    final_kernel<<<(NF + 127) / 128, 128>>>(p0, v0e, outp);
}

// round 4
// speedup vs baseline: 1.4386x; 1.4386x over previous
#include <cuda_runtime.h>
#include <math.h>
#include <stdint.h>

#define NF 3000
#define NB 1500
#define KNB 64

// -------------------- global scratch (no runtime allocation allowed) ----------
__device__ float g_p1[NF * 3];
__device__ float g_ff[NF * 9];

__device__ int   g_idxF[NF * KNB];
__device__ int   g_cbF [NF * KNB];
__device__ float g_w8F [NF * KNB * 8];
__device__ int   g_cntF[NF];

__device__ int   g_idxB[NF * KNB];
__device__ int   g_cbB [NF * KNB];
__device__ float g_w8B [NF * KNB * 8];
__device__ int   g_cntB[NF];

__device__ float g_out0[NF * 3 * 96];
__device__ float g_out1[NF * 3 * 64];
__device__ float g_out2[NF * 3 * 64];
__device__ float g_out3[NF * 3 * 64];
__device__ float g_out4[NF * 3 * 3];

__device__ float g_A[(size_t)NF * 3 * 64 * 96];   // GEMM input scratch (max layer1)

// -------------------- helpers -------------------------------------------------
__device__ __forceinline__ float sgnf(float v) {
    return (v > 0.f) ? 1.f : ((v < 0.f) ? -1.f : 0.f);
}

__device__ __forceinline__ uint32_t f2tf32(float f) {
    uint32_t r;
    asm("cvt.rna.tf32.f32 %0, %1;" : "=r"(r) : "f"(f));
    return r;
}

// Per-edge weight computation: offset (dx,dy,dz) = p_in[j] - p_out[n]
__device__ void edge_weights(float dx, float dy, float dz, float* w8, int* cbase)
{
    const float inv_r = 1.f / 3.f;     // radius = EXTENT*0.5 = 3.0
    float x = dx * inv_r, y = dy * inv_r, z = dz * inv_r;
    float sq = (x * x + y * y) + z * z;

    float win = 1.f - sq;
    win = win * win * win;
    win = fminf(fmaxf(win, 0.f), 1.f);

    // _ball_to_cube
    float norm  = sqrtf(fmaxf(sq, 1e-8f));
    float xy_sq = x * x + y * y;
    bool  polar = (1.25f * z * z > xy_sq);
    float s_p = sqrtf(3.f * norm / (norm + fabsf(z) + 1e-8f));
    float s_e = norm / sqrtf(fmaxf(xy_sq, 1e-8f));
    float cx = polar ? x * s_p : x * s_e;
    float cy = polar ? y * s_p : y * s_e;
    float cz = polar ? sgnf(z) * norm : 1.5f * z;

    float nxy = sqrtf(fmaxf(cx * cx + cy * cy, 1e-8f));
    bool  xdom = (fabsf(cy) <= fabsf(cx));
    float sx = (fabsf(cx) > 1e-8f) ? cx : 1.f;
    float sy = (fabsf(cy) > 1e-8f) ? cy : 1.f;
    const float FOPI = 1.27323954473516268615f;  // 4/pi
    float bx1 = sgnf(cx) * nxy;
    float by1 = bx1 * FOPI * atanf(cy / sx);
    float by2 = sgnf(cy) * nxy;
    float bx2 = by2 * FOPI * atanf(cx / sy);
    float bx = xdom ? bx1 : bx2;
    float by = xdom ? by1 : by2;
    if (cx * cx + cy * cy < 1e-8f) { bx = 0.f; by = 0.f; }
    float bz = cz;
    if (sq < 1e-8f) { bx = 0.f; by = 0.f; bz = 0.f; }

    float bb[3] = {bx, by, bz};
    float f[3];
    int   c0[3];
#pragma unroll
    for (int ax = 0; ax < 3; ax++) {
        float co = (bb[ax] * 0.5f + 0.5f) * 3.f;       // (KS-1)=3
        co = fminf(fmaxf(co, 0.f), 3.f);
        int ci = (int)floorf(co);
        ci = min(max(ci, 0), 2);
        c0[ax] = ci;
        f[ax] = co - (float)ci;
    }
    *cbase = (c0[0] * 4 + c0[1]) * 4 + c0[2];
#pragma unroll
    for (int r = 0; r < 8; r++) {
        int i = (r >> 2) & 1, j = (r >> 1) & 1, l = r & 1;
        float w = (i ? f[0] : 1.f - f[0]) * (j ? f[1] : 1.f - f[1]) * (l ? f[2] : 1.f - f[2]);
        w8[r] = w * win;
    }
}

// -------------------- kernel 1: prep -----------------------------------------
__global__ void prep_kernel(const float* __restrict__ p0, const float* __restrict__ v0,
                            const float* __restrict__ a, const float* __restrict__ other,
                            const float* __restrict__ v0e)
{
    int n = blockIdx.x * blockDim.x + threadIdx.x;
    if (n >= NF) return;
#pragma unroll
    for (int j = 0; j < 3; j++) {
        float v0v = v0[n * 3 + j], av = a[n * 3 + j];
        float v1 = v0v + 0.1f * av;
        float p1 = p0[n * 3 + j] + 0.1f * (v0v + v1) * 0.5f;
        g_p1[n * 3 + j] = p1;
        g_ff[n * 9 + 0 + j] = v1;                // s=0 : v1
        g_ff[n * 9 + 3 + j] = other[n * 3 + j];  // s=1 : other_feats
        g_ff[n * 9 + 6 + j] = v0e[n * 3 + j];    // s=2 : v0_enc
    }
}

// -------------------- kernel 2: neighbor build (fluid or box) -----------------
__global__ void nbr_kernel(const float* __restrict__ pts, int npts,
                           const float* __restrict__ mask, int self_exclude,
                           int* __restrict__ idx_out, int* __restrict__ cb_out,
                           float* __restrict__ w8_out, int* __restrict__ cnt_out)
{
    int n = blockIdx.x;
    __shared__ float sd2[512];
    __shared__ int   sidx[512];
    __shared__ int   scnt;
    float qx = g_p1[n * 3], qy = g_p1[n * 3 + 1], qz = g_p1[n * 3 + 2];
    if (threadIdx.x == 0) scnt = 0;
    __syncthreads();

    for (int j = threadIdx.x; j < npts; j += blockDim.x) {
        if (self_exclude && j == n) continue;
        if (mask && mask[j] <= 0.f) continue;
        float dx = pts[j * 3] - qx, dy = pts[j * 3 + 1] - qy, dz = pts[j * 3 + 2] - qz;
        float d2 = (dx * dx + dy * dy) + dz * dz;
        if (d2 < 9.0f) {
            int p = atomicAdd(&scnt, 1);
            if (p < 512) { sd2[p] = d2; sidx[p] = j; }
        }
    }
    __syncthreads();
    int cnt = min(scnt, 512);

    if (cnt > 1) {
        int P = 1;
        while (P < cnt) P <<= 1;
        for (int i = cnt + threadIdx.x; i < P; i += blockDim.x) { sd2[i] = 3.0e38f; sidx[i] = 0x7fffffff; }
        __syncthreads();
        for (int k = 2; k <= P; k <<= 1) {
            for (int j2 = k >> 1; j2 > 0; j2 >>= 1) {
                for (int i = threadIdx.x; i < P; i += blockDim.x) {
                    int ixj = i ^ j2;
                    if (ixj > i) {
                        float a = sd2[i], b = sd2[ixj];
                        int ia = sidx[i], ib = sidx[ixj];
                        bool agtb = (a > b) || ((a == b) && (ia > ib));
                        bool up = ((i & k) == 0);
                        if (agtb == up) { sd2[i] = b; sd2[ixj] = a; sidx[i] = ib; sidx[ixj] = ia; }
                    }
                }
                __syncthreads();
            }
        }
    }

    if (cnt > KNB) cnt = KNB;
    if (threadIdx.x == 0) cnt_out[n] = cnt;
    if ((int)threadIdx.x < cnt) {
        int j = sidx[threadIdx.x];
        float dx = pts[j * 3] - qx, dy = pts[j * 3 + 1] - qy, dz = pts[j * 3 + 2] - qz;
        float w8[8];
        int cb;
        edge_weights(dx, dy, dz, w8, &cb);
        int e = n * KNB + threadIdx.x;
        idx_out[e] = j;
        cb_out[e] = cb;
#pragma unroll
        for (int r = 0; r < 8; r++) w8_out[e * 8 + r] = w8[r];
    }
}

// -------------------- kernel 3: phase-2 (cf + co + df -> out0) ----------------
__global__ void phase2_kernel(const float* __restrict__ box_feats,
                              const float* __restrict__ k0f, const float* __restrict__ b0f,
                              const float* __restrict__ k0o, const float* __restrict__ b0o,
                              const float* __restrict__ wdf, const float* __restrict__ bdf)
{
    int n = blockIdx.x, tid = threadIdx.x;
    __shared__ float cF[576];   // 64 cells x 9 (s*3+c)
    __shared__ float cB[64];
    for (int i = tid; i < 576; i += blockDim.x) cF[i] = 0.f;
    if (tid < 64) cB[tid] = 0.f;
    __syncthreads();

    int cntF = g_cntF[n];
    for (int e = tid; e < cntF; e += blockDim.x) {
        int j = g_idxF[n * KNB + e];
        int cb = g_cbF[n * KNB + e];
        const float* w = &g_w8F[(n * KNB + e) * 8];
        float fj[9];
#pragma unroll
        for (int c = 0; c < 9; c++) fj[c] = g_ff[j * 9 + c];
#pragma unroll
        for (int r = 0; r < 8; r++) {
            int l = cb + ((r >> 2) & 1) * 16 + ((r >> 1) & 1) * 4 + (r & 1);
            float wr = w[r];
#pragma unroll
            for (int c = 0; c < 9; c++) atomicAdd(&cF[l * 9 + c], wr * fj[c]);
        }
    }
    int cntB = g_cntB[n];
    for (int e = tid; e < cntB; e += blockDim.x) {
        int j = g_idxB[n * KNB + e];
        int cb = g_cbB[n * KNB + e];
        const float* w = &g_w8B[(n * KNB + e) * 8];
        float bf = box_feats[j];
#pragma unroll
        for (int r = 0; r < 8; r++) {
            int l = cb + ((r >> 2) & 1) * 16 + ((r >> 1) & 1) * 4 + (r & 1);
            atomicAdd(&cB[l], w[r] * bf);
        }
    }
    __syncthreads();

    if (tid < 96) {
        int s = tid / 32, o = tid % 32;
        float co = b0o[o];
        for (int l = 0; l < 64; l++) co += cB[l] * k0o[l * 32 + o];
        float cf = b0f[o];
        for (int l = 0; l < 64; l++) {
#pragma unroll
            for (int c = 0; c < 3; c++) cf += cF[l * 9 + s * 3 + c] * k0f[(l * 3 + c) * 32 + o];
        }
        float df = bdf[o];
#pragma unroll
        for (int c = 0; c < 3; c++) df += g_ff[n * 9 + s * 3 + c] * wdf[c * 32 + o];
        int base = n * 288 + s * 96;
        g_out0[base + o]      = co;   // concat order: [co, cf, df]
        g_out0[base + 32 + o] = cf;
        g_out0[base + 64 + o] = df;
    }
}

// -------------------- kernel 4: per-point cell scatter (fluid edges) ----------
// prev: 3000 rows of (3*C) pre-relu features. Writes A (9000 x 64C), row = n*3+s.
__global__ void scatter_kernel(const float* __restrict__ prev, float* __restrict__ Aout, int C)
{
    int n = blockIdx.x;
    int SC = 3 * C;
    int tid = threadIdx.x;         // one channel (s*C+c) per thread, blockDim = SC
    extern __shared__ float cell[];   // [64][SC]
    __shared__ float ew[KNB * 8];
    __shared__ int   ej[KNB];
    __shared__ int   ecb[KNB];

    for (int l = 0; l < 64; l++) cell[l * SC + tid] = 0.f;
    int cnt = g_cntF[n];
    if (tid < cnt) { ej[tid] = g_idxF[n * KNB + tid]; ecb[tid] = g_cbF[n * KNB + tid]; }
    for (int i = tid; i < cnt * 8; i += blockDim.x) ew[i] = g_w8F[n * KNB * 8 + i];
    __syncthreads();

    for (int e = 0; e < cnt; e++) {
        float h = fmaxf(prev[(size_t)ej[e] * SC + tid], 0.f);
        int cb = ecb[e];
        const float* w = &ew[e * 8];
        cell[(cb + 0)  * SC + tid] += w[0] * h;
        cell[(cb + 1)  * SC + tid] += w[1] * h;
        cell[(cb + 4)  * SC + tid] += w[2] * h;
        cell[(cb + 5)  * SC + tid] += w[3] * h;
        cell[(cb + 16) * SC + tid] += w[4] * h;
        cell[(cb + 17) * SC + tid] += w[5] * h;
        cell[(cb + 20) * SC + tid] += w[6] * h;
        cell[(cb + 21) * SC + tid] += w[7] * h;
    }
    __syncthreads();

    int s = tid / C, c = tid % C;
    int Kdim = 64 * C;
    float* dst = Aout + (size_t)(n * 3 + s) * Kdim + c;
    for (int l = 0; l < 64; l++) dst[l * C] = cell[l * SC + tid];
}

// -------------------- kernel 5: TF32 tensor-core GEMM -------------------------
// Out[row,o] = sum_k A[row,k]*Bk[k,o] + sum_c relu(prev[row,c])*wd[c,o]
//              + bc[o]+bd[o] + (res ? prev[row,o] : 0).   N = 64 fixed.
// CTA: 64 rows x 64 cols, 128 threads = 4 warps (2M x 2N), warp tile m32 x n32.
// K staged 32 per iteration, register-prefetch double buffer, tf32 RNA staging.
#define AS_STRIDE 36
#define BS_STRIDE 72
__global__ void __launch_bounds__(128) gemm_tf32_kernel(
    const float* __restrict__ A, const float* __restrict__ Bk,
    const float* __restrict__ prev, const float* __restrict__ wd,
    const float* __restrict__ bc, const float* __restrict__ bd,
    float* __restrict__ Out, int M, int K, int C, int res)
{
    __shared__ uint32_t As[64 * AS_STRIDE];
    __shared__ uint32_t Bs[32 * BS_STRIDE];

    int tid = threadIdx.x;
    int warp = tid >> 5, lane = tid & 31;
    int warp_m = warp >> 1, warp_n = warp & 1;
    int g = lane >> 2, tg = lane & 3;
    int rowBase = blockIdx.x * 64;

    float acc[2][4][4];
#pragma unroll
    for (int i = 0; i < 2; i++)
#pragma unroll
        for (int j = 0; j < 4; j++)
#pragma unroll
            for (int q = 0; q < 4; q++) acc[i][j][q] = 0.f;

    const int stages0 = K / 32, stages1 = C / 32;
    const int S = stages0 + stages1;

    // A staging map: float4 id f = tid + q*128 (q=0..3): row = f>>3, c4 = (f&7)*4
    // B staging map: float4 id f = tid + q*128: krow = f>>4, c4 = (f&15)*4
    float4 pa[4], pb[4];

    auto load_stage = [&](int s) {
        int seg = (s >= stages0);
        const float* Ag = seg ? prev : A;
        const float* Bg = seg ? wd : Bk;
        int Ks = seg ? C : K;
        int k0 = seg ? (s - stages0) * 32 : s * 32;
#pragma unroll
        for (int q = 0; q < 4; q++) {
            int f = tid + q * 128;
            int r = rowBase + (f >> 3);
            if (r >= M) r = M - 1;
            int kc = k0 + ((f & 7) << 2);
            pa[q] = *(const float4*)(Ag + (size_t)r * Ks + kc);
            if (seg) {
                pa[q].x = fmaxf(pa[q].x, 0.f); pa[q].y = fmaxf(pa[q].y, 0.f);
                pa[q].z = fmaxf(pa[q].z, 0.f); pa[q].w = fmaxf(pa[q].w, 0.f);
            }
            int kr = k0 + (f >> 4);
            int cc = (f & 15) << 2;
            pb[q] = *(const float4*)(Bg + (size_t)kr * 64 + cc);
        }
    };

    auto store_stage = [&]() {
#pragma unroll
        for (int q = 0; q < 4; q++) {
            int f = tid + q * 128;
            uint32_t* ad = &As[(f >> 3) * AS_STRIDE + ((f & 7) << 2)];
            ad[0] = f2tf32(pa[q].x); ad[1] = f2tf32(pa[q].y);
            ad[2] = f2tf32(pa[q].z); ad[3] = f2tf32(pa[q].w);
            uint32_t* bdst = &Bs[(f >> 4) * BS_STRIDE + ((f & 15) << 2)];
            bdst[0] = f2tf32(pb[q].x); bdst[1] = f2tf32(pb[q].y);
            bdst[2] = f2tf32(pb[q].z); bdst[3] = f2tf32(pb[q].w);
        }
    };

    load_stage(0);
    for (int s = 0; s < S; s++) {
        store_stage();
        __syncthreads();
        if (s + 1 < S) load_stage(s + 1);

        // MMA over the 32-wide K stage (4 sub-steps of k8)
#pragma unroll
        for (int k8 = 0; k8 < 32; k8 += 8) {
            uint32_t af[2][4];
#pragma unroll
            for (int i2 = 0; i2 < 2; i2++) {
                int r0 = warp_m * 32 + i2 * 16 + g;
                af[i2][0] = As[r0 * AS_STRIDE + k8 + tg];
                af[i2][1] = As[(r0 + 8) * AS_STRIDE + k8 + tg];
                af[i2][2] = As[r0 * AS_STRIDE + k8 + tg + 4];
                af[i2][3] = As[(r0 + 8) * AS_STRIDE + k8 + tg + 4];
            }
#pragma unroll
            for (int j = 0; j < 4; j++) {
                int n0 = warp_n * 32 + j * 8;
                uint32_t b0 = Bs[(k8 + tg) * BS_STRIDE + n0 + g];
                uint32_t b1 = Bs[(k8 + tg + 4) * BS_STRIDE + n0 + g];
#pragma unroll
                for (int i2 = 0; i2 < 2; i2++) {
                    asm volatile(
                        "mma.sync.aligned.m16n8k8.row.col.f32.tf32.tf32.f32 "
                        "{%0,%1,%2,%3}, {%4,%5,%6,%7}, {%8,%9}, {%0,%1,%2,%3};\n"
                        : "+f"(acc[i2][j][0]), "+f"(acc[i2][j][1]),
                          "+f"(acc[i2][j][2]), "+f"(acc[i2][j][3])
                        : "r"(af[i2][0]), "r"(af[i2][1]), "r"(af[i2][2]), "r"(af[i2][3]),
                          "r"(b0), "r"(b1));
                }
            }
        }
        __syncthreads();
    }

    // epilogue
#pragma unroll
    for (int i2 = 0; i2 < 2; i2++) {
#pragma unroll
        for (int j = 0; j < 4; j++) {
            int col = warp_n * 32 + j * 8 + tg * 2;
#pragma unroll
            for (int q = 0; q < 4; q++) {
                int row = rowBase + warp_m * 32 + i2 * 16 + g + ((q >= 2) ? 8 : 0);
                int c = col + (q & 1);
                if (row < M) {
                    float v = acc[i2][j][q] + bc[c] + bd[c];
                    if (res) v += prev[(size_t)row * C + c];
                    Out[(size_t)row * 64 + c] = v;
                }
            }
        }
    }
}

// -------------------- kernel 6: last layer (64C -> 3) -------------------------
__global__ void out4_kernel(const float* __restrict__ A, const float* __restrict__ kern,
                            const float* __restrict__ prev, const float* __restrict__ wd,
                            const float* __restrict__ bc, const float* __restrict__ bd,
                            float* __restrict__ out4, int M, int K)
{
    int warp = (blockIdx.x * blockDim.x + threadIdx.x) >> 5;
    int lane = threadIdx.x & 31;
    if (warp >= M) return;
    float a0 = 0.f, a1 = 0.f, a2 = 0.f;
    const float* Ar = A + (size_t)warp * K;
    for (int k = lane; k < K; k += 32) {
        float av = Ar[k];
        a0 += av * kern[k * 3 + 0];
        a1 += av * kern[k * 3 + 1];
        a2 += av * kern[k * 3 + 2];
    }
    const float* pr = prev + (size_t)warp * 64;
    for (int c = lane; c < 64; c += 32) {
        float h = fmaxf(pr[c], 0.f);
        a0 += h * wd[c * 3 + 0];
        a1 += h * wd[c * 3 + 1];
        a2 += h * wd[c * 3 + 2];
    }
#pragma unroll
    for (int off = 16; off > 0; off >>= 1) {
        a0 += __shfl_down_sync(0xffffffffu, a0, off);
        a1 += __shfl_down_sync(0xffffffffu, a1, off);
        a2 += __shfl_down_sync(0xffffffffu, a2, off);
    }
    if (lane == 0) {
        out4[warp * 3 + 0] = a0 + bc[0] + bd[0];
        out4[warp * 3 + 1] = a1 + bc[1] + bd[1];
        out4[warp * 3 + 2] = a2 + bc[2] + bd[2];
    }
}

// -------------------- kernel 7: final outputs ---------------------------------
__global__ void final_kernel(const float* __restrict__ p0, const float* __restrict__ v0e,
                             float* __restrict__ outp)
{
    int n = blockIdx.x * blockDim.x + threadIdx.x;
    if (n >= NF) return;
#pragma unroll
    for (int j = 0; j < 3; j++) {
        float o0 = g_out4[n * 9 + j];                 // s=0 row
        float corr = o0 * 0.25f * (1.f / 16.f);
        float pc = g_p1[n * 3 + j] + corr;
        outp[n * 3 + j] = pc;                          // p_c
        outp[9000 + n * 3 + j] = (pc - p0[n * 3 + j]) / 0.1f;  // v_c
        outp[18000 + n * 6 + 0 + j] = g_out4[n * 9 + 3 + j] * 0.25f;  // m_matrix s=1
        outp[18000 + n * 6 + 3 + j] = g_out4[n * 9 + 6 + j] * 0.25f;  // m_matrix s=2
        outp[36000 + n * 3 + j] = v0e[n * 3 + j];      // state_feats
    }
}

// -------------------- launch --------------------------------------------------
template <typename T>
static T* sym_addr(const void* sym)
{
    void* p = nullptr;
    cudaGetSymbolAddress(&p, sym);
    return (T*)p;
}

extern "C" void kernel_launch(void* const* d_in, const int* in_sizes, int n_in,
                              void* d_out, int out_size)
{
    (void)n_in; (void)out_size;
    const float* v0e       = (const float*)d_in[1];
    const float* p0        = (const float*)d_in[2];
    const float* v0        = (const float*)d_in[3];
    const float* a         = (const float*)d_in[4];
    const float* other     = (const float*)d_in[5];
    const float* box       = (const float*)d_in[6];
    const float* box_feats = (const float*)d_in[7];
    const float* box_mask  = (const float*)d_in[9];
    const float* k0f = (const float*)d_in[10];
    const float* b0f = (const float*)d_in[11];
    const float* k0o = (const float*)d_in[12];
    const float* b0o = (const float*)d_in[13];
    const float* wdf = (const float*)d_in[14];
    const float* bdf = (const float*)d_in[15];

    // Resolve deep-layer weights 16..31 BY SIZE (robust to metadata ordering).
    const float* kcA[5] = {0, 0, 0, 0, 0};
    const float* wdA[5] = {0, 0, 0, 0, 0};
    const float* b64[6] = {0, 0, 0, 0, 0, 0};
    const float* b3[2]  = {0, 0};
    int n262 = 0, n4096 = 0, nb64 = 0, nb3 = 0;
    for (int i = 16; i < 32; i++) {
        const float* p = (const float*)d_in[i];
        switch (in_sizes[i]) {
            case 393216: kcA[1] = p; break;
            case 262144: if (n262++ == 0) kcA[2] = p; else kcA[3] = p; break;
            case 12288:  kcA[4] = p; break;
            case 6144:   wdA[1] = p; break;
            case 4096:   if (n4096++ == 0) wdA[2] = p; else wdA[3] = p; break;
            case 192:    wdA[4] = p; break;
            case 64:     if (nb64 < 6) b64[nb64++] = p; break;
            case 3:      if (nb3 < 2) b3[nb3++] = p; break;
            default: break;
        }
    }
    const float* bc1 = b64[0]; const float* bd1 = b64[1];
    const float* bc2 = b64[2]; const float* bd2 = b64[3];
    const float* bc3 = b64[4]; const float* bd3 = b64[5];
    const float* bc4 = b3[0];  const float* bd4 = b3[1];

    float* outp = (float*)d_out;

    float* pp1   = sym_addr<float>(g_p1);
    int*   pidxF = sym_addr<int>(g_idxF);
    int*   pcbF  = sym_addr<int>(g_cbF);
    float* pw8F  = sym_addr<float>(g_w8F);
    int*   pcntF = sym_addr<int>(g_cntF);
    int*   pidxB = sym_addr<int>(g_idxB);
    int*   pcbB  = sym_addr<int>(g_cbB);
    float* pw8B  = sym_addr<float>(g_w8B);
    int*   pcntB = sym_addr<int>(g_cntB);
    float* pout0 = sym_addr<float>(g_out0);
    float* pout1 = sym_addr<float>(g_out1);
    float* pout2 = sym_addr<float>(g_out2);
    float* pout3 = sym_addr<float>(g_out3);
    float* pout4 = sym_addr<float>(g_out4);
    float* pA    = sym_addr<float>(g_A);

    cudaFuncSetAttribute(scatter_kernel, cudaFuncAttributeMaxDynamicSharedMemorySize,
                         64 * 288 * (int)sizeof(float));

    prep_kernel<<<(NF + 127) / 128, 128>>>(p0, v0, a, other, v0e);
    nbr_kernel<<<NF, 128>>>(pp1, NF, nullptr, 1, pidxF, pcbF, pw8F, pcntF);
    nbr_kernel<<<NF, 128>>>(box, NB, box_mask, 0, pidxB, pcbB, pw8B, pcntB);
    phase2_kernel<<<NF, 128>>>(box_feats, k0f, b0f, k0o, b0o, wdf, bdf);

    const int Mrows = NF * 3;  // 9000
    const int gemmGrid = (Mrows + 63) / 64;   // 141 CTAs

    // layer 1: C=96, K=6144, no residual
    scatter_kernel<<<NF, 288, 64 * 288 * sizeof(float)>>>(pout0, pA, 96);
    gemm_tf32_kernel<<<gemmGrid, 128>>>(pA, kcA[1], pout0, wdA[1], bc1, bd1, pout1, Mrows, 6144, 96, 0);

    // layer 2: C=64, K=4096, residual
    scatter_kernel<<<NF, 192, 64 * 192 * sizeof(float)>>>(pout1, pA, 64);
    gemm_tf32_kernel<<<gemmGrid, 128>>>(pA, kcA[2], pout1, wdA[2], bc2, bd2, pout2, Mrows, 4096, 64, 1);

    // layer 3: C=64, K=4096, residual
    scatter_kernel<<<NF, 192, 64 * 192 * sizeof(float)>>>(pout2, pA, 64);
    gemm_tf32_kernel<<<gemmGrid, 128>>>(pA, kcA[3], pout2, wdA[3], bc3, bd3, pout3, Mrows, 4096, 64, 1);

    // layer 4: C=64 -> 3 outputs
    scatter_kernel<<<NF, 192, 64 * 192 * sizeof(float)>>>(pout3, pA, 64);
    out4_kernel<<<(Mrows * 32 + 255) / 256, 256>>>(pA, kcA[4], pout3, wdA[4], bc4, bd4, pout4, Mrows, 4096);

    final_kernel<<<(NF + 127) / 128, 128>>>(p0, v0e, outp);
}